// round 17
// baseline (speedup 1.0000x reference)
#include <cuda_runtime.h>
#include <cuda_fp16.h>
#include <math.h>
#include <stdint.h>

#define B_   64
#define T_   512
#define IN_  128
#define H_   512
#define G4_  2048
#define OUT_ 128
#define M_   (B_ * T_)   // 32768

#define FBLK 128    // 64 layer-0 + 64 layer-1 blocks
#define FTHR 128    // 4 warps per block (warp = 16 batch rows x 32 gate cols)
#define NGRP 8      // barrier groups (16 blocks each)

// ---------------- scratch (static device memory; no allocs) ----------------
__device__ unsigned int g_bars[NGRP * 64];          // group counters, 256B apart
__device__ __half g_x16[(size_t)M_ * IN_];          // x in fp16
__device__ __half g_h0[2 * B_ * H_];                // layer-0 h ping-pong (fp16)
__device__ __half g_h1[2 * B_ * H_];                // layer-1 h ping-pong (fp16)

// ======================= helpers ==============================
__device__ __forceinline__ uint32_t smem_u32(const void* p) {
    uint32_t a;
    asm("{ .reg .u64 t; cvta.to.shared.u64 t, %1; cvt.u32.u64 %0, t; }"
        : "=r"(a) : "l"(p));
    return a;
}

#define LDSM_X4(r, addr) \
    asm volatile("ldmatrix.sync.aligned.m8n8.x4.shared.b16 {%0,%1,%2,%3}, [%4];" \
        : "=r"((r)[0]), "=r"((r)[1]), "=r"((r)[2]), "=r"((r)[3]) : "r"(addr))

__device__ __forceinline__ void mma_f16(float* d, const uint32_t* a, const uint32_t* b) {
    asm volatile("mma.sync.aligned.m16n8k16.row.col.f32.f16.f16.f32 "
        "{%0,%1,%2,%3}, {%4,%5,%6,%7}, {%8,%9}, {%0,%1,%2,%3};"
        : "+f"(d[0]), "+f"(d[1]), "+f"(d[2]), "+f"(d[3])
        : "r"(a[0]), "r"(a[1]), "r"(a[2]), "r"(a[3]), "r"(b[0]), "r"(b[1]));
}

#define CP_ASYNC16(dst, src) \
    asm volatile("cp.async.cg.shared.global [%0], [%1], 16;" :: "r"(dst), "l"(src))
#define CP_COMMIT() asm volatile("cp.async.commit_group;" ::: "memory")
#define CP_WAIT(n)  asm volatile("cp.async.wait_group %0;" :: "n"(n) : "memory")

__device__ __forceinline__ float sigmoid_fast(float x) {
    float e, r;
    asm("ex2.approx.f32 %0, %1;" : "=f"(e) : "f"(-1.4426950408889634f * x));
    asm("rcp.approx.f32 %0, %1;" : "=f"(r) : "f"(1.f + e));
    return r;
}
__device__ __forceinline__ float tanh_fast(float x) {
    float y;
    asm("tanh.approx.f32 %0, %1;" : "=f"(y) : "f"(x));
    return y;
}

// ---------------------------------------------------------------------------
// x fp32 -> fp16 convert (vectorized, 4 elems/thread); resets barrier counters
// ---------------------------------------------------------------------------
__global__ __launch_bounds__(256) void convert_x_kernel(
    const float* __restrict__ in, __half* __restrict__ out, int n4,
    unsigned* bar_reset)
{
    if (bar_reset && blockIdx.x == 0 && threadIdx.x < NGRP)
        bar_reset[threadIdx.x * 64] = 0u;
    int i = blockIdx.x * 256 + threadIdx.x;
    if (i < n4) {
        float4 v = ((const float4*)in)[i];
        __half2 lo = __floats2half2_rn(v.x, v.y);
        __half2 hi = __floats2half2_rn(v.z, v.w);
        ((__half2*)out)[i * 2]     = lo;
        ((__half2*)out)[i * 2 + 1] = hi;
    }
}

// ---------------------------------------------------------------------------
// FUSED two-layer persistent LSTM — warp-synchronous steps, dual acc chains.
// Blocks 0..63 (L0): resident W_hh0 (32x520) + W_ih0 (32x136); per stage:
//   x tile (chunk 0) + 4 chunks h0[t-1]; gates in registers (accA+accB).
// Blocks 64..127 (L1): resident [W_ih1;W_hh1]; 8 chunks [h0[t];h1[t-1]].
// Cell state in registers; only the inter-block barrier block-syncs.
// ---------------------------------------------------------------------------
#define WS0_STR   520
#define WIH_OFF   33280u
#define WIH_STR   136
#define HS0_OFF   41984u
#define HCW_BYTES 4352u             // 16*136*2 per chunk per warp
#define W0_STAGE  21760u            // 5 chunks
#define WS1_STR   1048
#define HS1_OFF   67072u
#define W1_STAGE  34816u            // 8 chunks
#define FUSED_SMEM 206336

__global__ __launch_bounds__(FTHR, 1) void lstm_fused_kernel(
    const __half* __restrict__ x16,
    const float* __restrict__ Whh0, const float* __restrict__ Wih0,
    const float* __restrict__ b_ih0, const float* __restrict__ b_hh0,
    const float* __restrict__ Wih1, const float* __restrict__ Whh1,
    const float* __restrict__ b_ih1, const float* __restrict__ b_hh1,
    __half* __restrict__ h0, __half* __restrict__ h1,
    unsigned* __restrict__ bars)
{
    extern __shared__ char sm8[];
    const int tx   = threadIdx.x;
    const int wid  = tx >> 5;
    const int lane = tx & 31;
    const bool isL0 = blockIdx.x < 64;
    const int j0   = (blockIdx.x & 63) * 8;
    const int grp  = blockIdx.x >> 4;

    const uint32_t smb = smem_u32(sm8);
    __half* ws = (__half*)sm8;

    const int arow_l = (lane & 7) + ((lane >> 3) & 1) * 8;
    const int acol_l = (lane >> 4) * 8;
    const int brow_l = ((lane >> 4) & 1) * 8 + (lane & 7);
    const int bcol_l = ((lane >> 3) & 1) * 8;

    const int r0 = lane >> 2;
    const int u0 = (lane & 3) * 2;

    float bias_v[4][2];

    if (isL0) {
        for (int i = 0; i < 128; i++) {
            int idx = tx + i * 128;
            int cc = idx >> 9, k = idx & 511;
            int gg = cc >> 3, u = cc & 7;
            ws[cc * WS0_STR + k] =
                __float2half(Whh0[(size_t)(gg * H_ + j0 + u) * H_ + k]);
        }
        for (int i = 0; i < 32; i++) {
            int idx = tx + i * 128;
            int cc = idx >> 7, k = idx & 127;
            int gg = cc >> 3, u = cc & 7;
            ws[(WIH_OFF >> 1) + cc * WIH_STR + k] =
                __float2half(Wih0[(size_t)(gg * H_ + j0 + u) * IN_ + k]);
        }
#pragma unroll
        for (int g = 0; g < 4; g++) {
            bias_v[g][0] = b_ih0[g * H_ + j0 + u0]     + b_hh0[g * H_ + j0 + u0];
            bias_v[g][1] = b_ih0[g * H_ + j0 + u0 + 1] + b_hh0[g * H_ + j0 + u0 + 1];
        }
    } else {
        for (int i = 0; i < 256; i++) {
            int idx = tx + i * 128;
            int cc = idx >> 10, k = idx & 1023;
            int gg = cc >> 3, u = cc & 7;
            size_t row = (size_t)(gg * H_ + j0 + u) * H_;
            float w = (k < 512) ? Wih1[row + k] : Whh1[row + k - 512];
            ws[cc * WS1_STR + k] = __float2half(w);
        }
#pragma unroll
        for (int g = 0; g < 4; g++) {
            bias_v[g][0] = b_ih1[g * H_ + j0 + u0]     + b_hh1[g * H_ + j0 + u0];
            bias_v[g][1] = b_ih1[g * H_ + j0 + u0 + 1] + b_hh1[g * H_ + j0 + u0 + 1];
        }
    }
    __syncthreads();

    float accA[4][4], accB[4][4];
    float cst[4];
#pragma unroll
    for (int e = 0; e < 4; e++) cst[e] = 0.f;

    const uint32_t hsb = smb + (isL0 ? HS0_OFF : HS1_OFF)
                       + (uint32_t)wid * (isL0 ? W0_STAGE : W1_STAGE);
    const int wrow0 = wid * 16;

    for (int s = 0; s <= T_; s++) {
        if (isL0 && s < T_) {
            // ================= layer-0 step s =================
            const int t = s;

            // chunk 0: full 16x128 x tile (256 vec16)
#pragma unroll
            for (int i = 0; i < 8; i++) {
                int idx = lane + i * 32;
                int r   = idx >> 4;
                int seg = idx & 15;
                const __half* src = x16 + ((size_t)(wrow0 + r) * T_ + t) * IN_ + seg * 8;
                CP_ASYNC16(hsb + (uint32_t)(r * 136 + seg * 8) * 2, src);
            }
            CP_COMMIT();

            if (t > 0) {
                const long long inoff = (long long)((t & 1) ^ 1) * B_ * H_;
#pragma unroll
                for (int c = 0; c < 4; c++) {
#pragma unroll
                    for (int i = 0; i < 8; i++) {
                        int idx = lane + i * 32;
                        int r   = idx >> 4;
                        int seg = idx & 15;
                        const __half* src = h0 + inoff
                            + (long long)(wrow0 + r) * H_ + c * 128 + seg * 8;
                        CP_ASYNC16(hsb + (uint32_t)(1 + c) * HCW_BYTES
                                   + (uint32_t)(r * 136 + seg * 8) * 2, src);
                    }
                    CP_COMMIT();
                }
            }

#pragma unroll
            for (int g = 0; g < 4; g++)
#pragma unroll
                for (int e = 0; e < 4; e++) { accA[g][e] = 0.f; accB[g][e] = 0.f; }

            // x-projection -> accA
            if (t > 0) { CP_WAIT(4); } else { CP_WAIT(0); }
            __syncwarp();
#pragma unroll
            for (int kk2 = 0; kk2 < 8; kk2++) {
                uint32_t a[4], bf0[4], bf1[4];
                LDSM_X4(a, hsb + (uint32_t)(arow_l * 136 + kk2 * 16 + acol_l) * 2);
                uint32_t bd = smb + WIH_OFF
                            + (uint32_t)(brow_l * WIH_STR + kk2 * 16 + bcol_l) * 2;
                LDSM_X4(bf0, bd);
                LDSM_X4(bf1, bd + (uint32_t)(16 * WIH_STR) * 2);
                mma_f16(accA[0], a, bf0);
                mma_f16(accA[1], a, bf0 + 2);
                mma_f16(accA[2], a, bf1);
                mma_f16(accA[3], a, bf1 + 2);
            }

            // h chunks: alternate accB / accA
            if (t > 0) {
                auto consume = [&](int c, float (*acc)[4]) {
                    const uint32_t hb = hsb + (uint32_t)(1 + c) * HCW_BYTES;
#pragma unroll
                    for (int kk2 = 0; kk2 < 8; kk2++) {
                        uint32_t a[4], bf0[4], bf1[4];
                        LDSM_X4(a, hb + (uint32_t)(arow_l * 136 + kk2 * 16 + acol_l) * 2);
                        int kg = c * 8 + kk2;
                        uint32_t bd = smb + (uint32_t)(brow_l * WS0_STR
                                                       + kg * 16 + bcol_l) * 2;
                        LDSM_X4(bf0, bd);
                        LDSM_X4(bf1, bd + (uint32_t)(16 * WS0_STR) * 2);
                        mma_f16(acc[0], a, bf0);
                        mma_f16(acc[1], a, bf0 + 2);
                        mma_f16(acc[2], a, bf1);
                        mma_f16(acc[3], a, bf1 + 2);
                    }
                };
                CP_WAIT(3); __syncwarp(); consume(0, accB);
                CP_WAIT(2); __syncwarp(); consume(1, accA);
                CP_WAIT(1); __syncwarp(); consume(2, accB);
                CP_WAIT(0); __syncwarp(); consume(3, accA);
            }

            const long long outoff = (long long)(t & 1) * B_ * H_;
#pragma unroll
            for (int e = 0; e < 4; e++) {
                int rr = e >> 1, uu = e & 1;
                float gi = bias_v[0][uu] + accA[0][e] + accB[0][e];
                float gf = bias_v[1][uu] + accA[1][e] + accB[1][e];
                float gc = bias_v[2][uu] + accA[2][e] + accB[2][e];
                float go = bias_v[3][uu] + accA[3][e] + accB[3][e];
                float i_ = sigmoid_fast(gi);
                float f_ = sigmoid_fast(gf);
                float g_ = tanh_fast(gc);
                float o_ = sigmoid_fast(go);
                float cn = f_ * cst[e] + i_ * g_;
                cst[e] = cn;
                int b = wrow0 + r0 + rr * 8;
                h0[outoff + (long long)b * H_ + j0 + u0 + uu] =
                    __float2half(o_ * tanh_fast(cn));
            }
        } else if (!isL0 && s >= 1) {
            // ================= layer-1 step t = s-1 =================
            const int t = s - 1;
            const long long in0 = (long long)(t & 1) * B_ * H_;
            const long long in1 = (long long)((t & 1) ^ 1) * B_ * H_;
            const int nch = (t == 0) ? 4 : 8;

#pragma unroll
            for (int c = 0; c < 8; c++) {
                if (c >= nch) break;
                const __half* sh = (c < 4) ? (h0 + in0) : (h1 + in1);
                int coff = (c < 4) ? c * 128 : (c - 4) * 128;
#pragma unroll
                for (int i = 0; i < 8; i++) {
                    int idx = lane + i * 32;
                    int r   = idx >> 4;
                    int seg = idx & 15;
                    const __half* src = sh + (long long)(wrow0 + r) * H_ + coff + seg * 8;
                    CP_ASYNC16(hsb + (uint32_t)c * HCW_BYTES
                               + (uint32_t)(r * 136 + seg * 8) * 2, src);
                }
                CP_COMMIT();
            }

#pragma unroll
            for (int g = 0; g < 4; g++)
#pragma unroll
                for (int e = 0; e < 4; e++) { accA[g][e] = 0.f; accB[g][e] = 0.f; }

            auto consume = [&](int c, float (*acc)[4]) {
                const uint32_t hb = hsb + (uint32_t)c * HCW_BYTES;
#pragma unroll
                for (int kk2 = 0; kk2 < 8; kk2++) {
                    uint32_t a[4], bf0[4], bf1[4];
                    LDSM_X4(a, hb + (uint32_t)(arow_l * 136 + kk2 * 16 + acol_l) * 2);
                    int kg = c * 8 + kk2;
                    uint32_t bd = smb + (uint32_t)(brow_l * WS1_STR
                                                   + kg * 16 + bcol_l) * 2;
                    LDSM_X4(bf0, bd);
                    LDSM_X4(bf1, bd + (uint32_t)(16 * WS1_STR) * 2);
                    mma_f16(acc[0], a, bf0);
                    mma_f16(acc[1], a, bf0 + 2);
                    mma_f16(acc[2], a, bf1);
                    mma_f16(acc[3], a, bf1 + 2);
                }
            };
            if (nch == 8) {
                CP_WAIT(7); __syncwarp(); consume(0, accA);
                CP_WAIT(6); __syncwarp(); consume(1, accB);
                CP_WAIT(5); __syncwarp(); consume(2, accA);
                CP_WAIT(4); __syncwarp(); consume(3, accB);
                CP_WAIT(3); __syncwarp(); consume(4, accA);
                CP_WAIT(2); __syncwarp(); consume(5, accB);
                CP_WAIT(1); __syncwarp(); consume(6, accA);
                CP_WAIT(0); __syncwarp(); consume(7, accB);
            } else {
                CP_WAIT(3); __syncwarp(); consume(0, accA);
                CP_WAIT(2); __syncwarp(); consume(1, accB);
                CP_WAIT(1); __syncwarp(); consume(2, accA);
                CP_WAIT(0); __syncwarp(); consume(3, accB);
            }

            const long long outoff = (long long)(t & 1) * B_ * H_;
#pragma unroll
            for (int e = 0; e < 4; e++) {
                int rr = e >> 1, uu = e & 1;
                float gi = bias_v[0][uu] + accA[0][e] + accB[0][e];
                float gf = bias_v[1][uu] + accA[1][e] + accB[1][e];
                float gc = bias_v[2][uu] + accA[2][e] + accB[2][e];
                float go = bias_v[3][uu] + accA[3][e] + accB[3][e];
                float i_ = sigmoid_fast(gi);
                float f_ = sigmoid_fast(gf);
                float g_ = tanh_fast(gc);
                float o_ = sigmoid_fast(go);
                float cn = f_ * cst[e] + i_ * g_;
                cst[e] = cn;
                int b = wrow0 + r0 + rr * 8;
                h1[outoff + (long long)b * H_ + j0 + u0 + uu] =
                    __float2half(o_ * tanh_fast(cn));
            }
        }

        // ---- two-level grid barrier between stages ----
        if (s < T_) {
            __syncthreads();
            if (tx == 0) {
                asm volatile("red.release.gpu.global.add.u32 [%0], %1;"
                             :: "l"(bars + grp * 64), "r"(1u) : "memory");
            }
            if (tx < NGRP) {
                unsigned target = (unsigned)(s + 1) * 16u;
                unsigned* p = bars + tx * 64;
                unsigned v;
                do {
                    asm volatile("ld.acquire.gpu.global.u32 %0, [%1];"
                                 : "=r"(v) : "l"(p) : "memory");
                } while (v < target);
            }
            __syncthreads();
        }
    }
}

// ---------------------------------------------------------------------------
// Final FC on fp16 h
// ---------------------------------------------------------------------------
__global__ __launch_bounds__(128) void fc_kernel(
    const __half* __restrict__ h, const float* __restrict__ Wfc,
    const float* __restrict__ bfc, float* __restrict__ out)
{
    __shared__ float hrow[H_];
    int b = blockIdx.x;
    for (int k = threadIdx.x; k < H_; k += 128)
        hrow[k] = __half2float(h[b * H_ + k]);
    __syncthreads();

    int o = threadIdx.x;
    float s = bfc[o];
    const float4* w4 = reinterpret_cast<const float4*>(Wfc + (size_t)o * H_);
    const float4* h4 = reinterpret_cast<const float4*>(hrow);
#pragma unroll 4
    for (int k = 0; k < H_ / 4; k++) {
        float4 w = w4[k];
        float4 hh = h4[k];
        s += w.x * hh.x + w.y * hh.y + w.z * hh.z + w.w * hh.w;
    }
    out[b * OUT_ + o] = s;
}

// ---------------------------------------------------------------------------
extern "C" void kernel_launch(void* const* d_in, const int* in_sizes, int n_in,
                              void* d_out, int out_size)
{
    const float* x     = (const float*)d_in[0];
    const float* W_ih0 = (const float*)d_in[1];
    const float* W_hh0 = (const float*)d_in[2];
    const float* b_ih0 = (const float*)d_in[3];
    const float* b_hh0 = (const float*)d_in[4];
    const float* W_ih1 = (const float*)d_in[5];
    const float* W_hh1 = (const float*)d_in[6];
    const float* b_ih1 = (const float*)d_in[7];
    const float* b_hh1 = (const float*)d_in[8];
    const float* W_fc  = (const float*)d_in[9];
    const float* b_fc  = (const float*)d_in[10];
    float* out = (float*)d_out;

    unsigned* bars;
    __half *x16, *h0, *h1;
    cudaGetSymbolAddress((void**)&bars, g_bars);
    cudaGetSymbolAddress((void**)&x16,  g_x16);
    cudaGetSymbolAddress((void**)&h0,   g_h0);
    cudaGetSymbolAddress((void**)&h1,   g_h1);

    cudaFuncSetAttribute(lstm_fused_kernel,
                         cudaFuncAttributeMaxDynamicSharedMemorySize, FUSED_SMEM);

    // convert x to fp16 (vectorized; also resets barrier counters)
    int n4 = (M_ * IN_) / 4;
    convert_x_kernel<<<(n4 + 255) / 256, 256>>>(x, x16, n4, bars);

    // fused two-layer recurrence
    lstm_fused_kernel<<<FBLK, FTHR, FUSED_SMEM>>>(
        x16, W_hh0, W_ih0, b_ih0, b_hh0,
        W_ih1, W_hh1, b_ih1, b_hh1, h0, h1, bars);

    // final FC on h1[t=511] (parity 1)
    fc_kernel<<<B_, 128>>>(h1 + (size_t)B_ * H_, W_fc, b_fc, out);
}